// round 1
// baseline (speedup 1.0000x reference)
#include <cuda_runtime.h>
#include <math.h>

#define Bx 256
#define Rn 20
#define Wn 100
#define Dn 128
#define Hn 64
#define NCOL (Dn*Hn)   // 8192
#define BT 32
#define CT 128

// Scratch (allocation-free rule: __device__ globals)
__device__ float g_user_emb[Bx*Rn*Dn];   // 2.62 MB
__device__ float g_item_emb[Bx*Rn*Dn];   // 2.62 MB
__device__ float g_q_emb[Bx*Dn];         // 128 KB
__device__ float g_V[Bx*Dn];             // 128 KB

// ---------------------------------------------------------------------------
// Kernel 1: doc embedding (tanh self-attention pooling over words)
// One block per doc. Embeddings gathered ONCE into smem; score dot fused
// into the gather (computed from the load registers, warp-reduced).
// ---------------------------------------------------------------------------
__global__ void doc_embed_kernel(const int* __restrict__ user,
                                 const int* __restrict__ item,
                                 const int* __restrict__ query,
                                 const float* __restrict__ emb,
                                 const float* __restrict__ w_self,
                                 const float* __restrict__ b_self) {
    extern __shared__ float sm[];
    float* we_s   = sm;                  // Wn*Dn = 12800 floats
    float* sscore = sm + Wn*Dn;          // Wn
    float* spart  = sscore + Wn;         // Dn
    int*   swords = (int*)(spart + Dn);  // Wn

    const int tid  = threadIdx.x;        // 256 threads
    const int lane = tid & 31;
    const int wid  = tid >> 5;
    const int doc  = blockIdx.x;

    const int* words;
    float* outp;
    if (doc < Bx*Rn)            { words = user + doc*Wn;              outp = g_user_emb + doc*Dn; }
    else if (doc < 2*Bx*Rn)     { int j = doc - Bx*Rn;   words = item  + j*Wn; outp = g_item_emb + j*Dn; }
    else                        { int j = doc - 2*Bx*Rn; words = query + j*Wn; outp = g_q_emb    + j*Dn; }

    if (tid < Wn) swords[tid] = words[tid];
    __syncthreads();

    const float4 ws4 = *(const float4*)(w_self + lane*4);
    const float  bs  = b_self[0];

    // Gather + fused score: warp w handles words w, w+8, ...
    for (int w = wid; w < Wn; w += 8) {
        const int word = swords[w];
        float4 e = *(const float4*)(emb + (size_t)word*Dn + lane*4);
        *(float4*)(we_s + w*Dn + lane*4) = e;
        float p = e.x*ws4.x + e.y*ws4.y + e.z*ws4.z + e.w*ws4.w;
        #pragma unroll
        for (int off = 16; off > 0; off >>= 1)
            p += __shfl_xor_sync(0xffffffffu, p, off);
        if (lane == 0) sscore[w] = tanhf(p + bs);
    }
    __syncthreads();

    // Softmax over the 100 words (single warp)
    if (wid == 0) {
        float m = -1e30f;
        for (int i = lane; i < Wn; i += 32) m = fmaxf(m, sscore[i]);
        #pragma unroll
        for (int off = 16; off > 0; off >>= 1)
            m = fmaxf(m, __shfl_xor_sync(0xffffffffu, m, off));
        float s = 0.f;
        for (int i = lane; i < Wn; i += 32) {
            float e = __expf(sscore[i] - m);
            sscore[i] = e;
            s += e;
        }
        #pragma unroll
        for (int off = 16; off > 0; off >>= 1)
            s += __shfl_xor_sync(0xffffffffu, s, off);
        float inv = 1.f / s;
        for (int i = lane; i < Wn; i += 32) sscore[i] *= inv;
    }
    __syncthreads();

    // Weighted sum: 256 threads = 2 halves of the word range per dim
    const int d    = tid & 127;
    const int half = tid >> 7;
    float acc = 0.f;
    const int w0 = half * (Wn/2);
    #pragma unroll 5
    for (int w = w0; w < w0 + Wn/2; ++w)
        acc += sscore[w] * we_s[w*Dn + d];
    if (half) spart[d] = acc;
    __syncthreads();
    if (!half) outp[d] = acc + spart[d];
}

// ---------------------------------------------------------------------------
// Kernel 2: fused  V[b,d] = sum_h tanh(q_b . Wq[:, d*64+h] + bq) * w_red[h]
// Batch-tiled GEMM (BT=32 batches reuse each Wq element), col tile CT=128.
// pq (8 MB) is never materialized.
// ---------------------------------------------------------------------------
__global__ void pq_kernel(const float* __restrict__ Wq,
                          const float* __restrict__ bq,
                          const float* __restrict__ w_red) {
    __shared__ __align__(16) float QsT[Dn][BT + 4];   // transposed, padded
    __shared__ float red[BT][CT + 1];

    const int tid  = threadIdx.x;        // 128 threads
    const int col0 = blockIdx.x * CT;
    const int b0   = blockIdx.y * BT;

    #pragma unroll 4
    for (int b = 0; b < BT; b++)
        QsT[tid][b] = g_q_emb[(b0 + b)*Dn + tid];
    __syncthreads();

    float acc[BT];
    #pragma unroll
    for (int b = 0; b < BT; b++) acc[b] = 0.f;

    const int col = col0 + tid;
    const float* wqp = Wq + col;
    #pragma unroll 4
    for (int k = 0; k < Dn; k++) {
        const float wv = wqp[(size_t)k * NCOL];
        const float4* q4 = (const float4*)(&QsT[k][0]);
        #pragma unroll
        for (int i = 0; i < BT/4; i++) {
            float4 q = q4[i];
            acc[4*i+0] += q.x * wv;
            acc[4*i+1] += q.y * wv;
            acc[4*i+2] += q.z * wv;
            acc[4*i+3] += q.w * wv;
        }
    }

    const float bqv = bq[col];
    const float wr  = w_red[col & (Hn-1)];
    #pragma unroll
    for (int b = 0; b < BT; b++)
        red[b][tid] = tanhf(acc[b] + bqv) * wr;
    __syncthreads();

    // Reduce groups of 64 cols: 64 sums, 2 threads each
    const int s    = tid >> 1;      // 0..63
    const int b    = s >> 1;        // 0..31
    const int grp  = s & 1;
    const int part = tid & 1;
    float r = 0.f;
    const int base = grp*64 + part*32;
    #pragma unroll
    for (int j = 0; j < 32; j++) r += red[b][base + j];
    r += __shfl_xor_sync(0xffffffffu, r, 1);
    if (part == 0) {
        const int dd = (col0 >> 6) + grp;
        g_V[(b0 + b)*Dn + dd] = r;
    }
}

// ---------------------------------------------------------------------------
// Kernel 3: review attention (softmax over R=20) + final outputs
// One block per batch.
// ---------------------------------------------------------------------------
__global__ void attn_kernel(const float* __restrict__ pf_ptr,
                            float* __restrict__ out) {
    __shared__ float v[Dn];
    __shared__ float r_u[32], r_i[32];
    const int tid  = threadIdx.x;   // 128
    const int lane = tid & 31;
    const int wid  = tid >> 5;
    const int b    = blockIdx.x;

    v[tid] = g_V[b*Dn + tid];
    __syncthreads();

    for (int rr = wid; rr < Rn; rr += 4) {
        const float* ue = g_user_emb + (b*Rn + rr)*Dn;
        const float* ie = g_item_emb + (b*Rn + rr)*Dn;
        float pu = 0.f, pi = 0.f;
        #pragma unroll
        for (int j = 0; j < 4; j++) {
            const int d = lane + 32*j;
            const float vv = v[d];
            pu += ue[d]*vv;
            pi += ie[d]*vv;
        }
        #pragma unroll
        for (int off = 16; off > 0; off >>= 1) {
            pu += __shfl_xor_sync(0xffffffffu, pu, off);
            pi += __shfl_xor_sync(0xffffffffu, pi, off);
        }
        if (lane == 0) { r_u[rr] = pu; r_i[rr] = pi; }
    }
    __syncthreads();

    if (wid < 2) {
        float* rs = wid ? r_i : r_u;
        float x = (lane < Rn) ? rs[lane] : -1e30f;
        float m = x;
        #pragma unroll
        for (int off = 16; off > 0; off >>= 1)
            m = fmaxf(m, __shfl_xor_sync(0xffffffffu, m, off));
        float e = (lane < Rn) ? __expf(x - m) : 0.f;
        float ss = e;
        #pragma unroll
        for (int off = 16; off > 0; off >>= 1)
            ss += __shfl_xor_sync(0xffffffffu, ss, off);
        if (lane < Rn) rs[lane] = e / ss;
    }
    __syncthreads();

    float ue_acc = 0.f, ie_acc = 0.f;
    #pragma unroll
    for (int rr = 0; rr < Rn; rr++) {
        ue_acc += r_u[rr] * g_user_emb[(b*Rn + rr)*Dn + tid];
        ie_acc += r_i[rr] * g_item_emb[(b*Rn + rr)*Dn + tid];
    }
    const float pf = pf_ptr[0];
    out[b*Dn + tid]        = ue_acc + pf * g_q_emb[b*Dn + tid];
    out[Bx*Dn + b*Dn + tid] = ie_acc;
}

// ---------------------------------------------------------------------------
extern "C" void kernel_launch(void* const* d_in, const int* in_sizes, int n_in,
                              void* d_out, int out_size) {
    const int*   user   = (const int*)  d_in[0];
    const int*   item   = (const int*)  d_in[1];
    const int*   query  = (const int*)  d_in[2];
    const float* emb    = (const float*)d_in[3];
    const float* w_self = (const float*)d_in[4];
    const float* b_self = (const float*)d_in[5];
    const float* Wq     = (const float*)d_in[6];
    const float* bq     = (const float*)d_in[7];
    const float* w_red  = (const float*)d_in[8];
    const float* pf     = (const float*)d_in[9];
    float* out = (float*)d_out;

    const int smem1 = (Wn*Dn + Wn + Dn + Wn) * 4;   // 52512 bytes (> 48KB, opt-in)
    cudaFuncSetAttribute(doc_embed_kernel,
                         cudaFuncAttributeMaxDynamicSharedMemorySize, smem1);

    doc_embed_kernel<<<2*Bx*Rn + Bx, 256, smem1>>>(user, item, query,
                                                   emb, w_self, b_self);

    dim3 g2(NCOL/CT, Bx/BT);   // (64, 8)
    pq_kernel<<<g2, CT>>>(Wq, bq, w_red);

    attn_kernel<<<Bx, Dn>>>(pf, out);
}

// round 3
// speedup vs baseline: 1.2892x; 1.2892x over previous
#include <cuda_runtime.h>
#include <math.h>

#define Bx 256
#define Rn 20
#define Wn 100
#define Dn 128
#define Hn 64
#define NCOL (Dn*Hn)   // 8192
#define BT 32
#define CT 128
#define NWPW 13        // max words per warp: ceil(100/8)

// Scratch (allocation-free rule: __device__ globals)
__device__ float g_user_emb[Bx*Rn*Dn];   // 2.62 MB
__device__ float g_item_emb[Bx*Rn*Dn];   // 2.62 MB
__device__ float g_q_emb[Bx*Dn];         // 128 KB
__device__ float g_V[Bx*Dn];             // 128 KB

// ---------------------------------------------------------------------------
// Kernel 1: doc embedding (tanh self-attention pooling over words).
// One block (256 thr = 8 warps) per doc. Gathered embeddings live in
// REGISTERS (13 float4/lane) across score + softmax + weighted-sum passes;
// only 100 scores + 8x128 partials touch smem (~4.5 KB/doc vs 102 KB before).
// ---------------------------------------------------------------------------
__global__ __launch_bounds__(256) void doc_embed_kernel(
        const int* __restrict__ user,
        const int* __restrict__ item,
        const int* __restrict__ query,
        const float* __restrict__ emb,
        const float* __restrict__ w_self,
        const float* __restrict__ b_self) {
    __shared__ float sscore[Wn];
    __shared__ int   swords[Wn];
    __shared__ __align__(16) float spart[8][Dn + 4];  // row = 528 B (16B-mult)

    const int tid  = threadIdx.x;
    const int lane = tid & 31;
    const int wid  = tid >> 5;
    const int doc  = blockIdx.x;

    const int* words;
    float* outp;
    if (doc < Bx*Rn)        { words = user + doc*Wn;                outp = g_user_emb + doc*Dn; }
    else if (doc < 2*Bx*Rn) { int j = doc - Bx*Rn;   words = item  + j*Wn; outp = g_item_emb + j*Dn; }
    else                    { int j = doc - 2*Bx*Rn; words = query + j*Wn; outp = g_q_emb    + j*Dn; }

    if (tid < Wn) swords[tid] = words[tid];
    __syncthreads();

    const float4 ws4 = *(const float4*)(w_self + lane*4);
    const float  bs  = b_self[0];

    // Gather: warp `wid` owns words wid, wid+8, ... — all loads issued first
    // (independent, high MLP), embeddings retained in registers.
    float4 e[NWPW];
    #pragma unroll
    for (int i = 0; i < NWPW; i++) {
        const int w = wid + 8*i;
        if (w < Wn) {
            const int word = swords[w];
            e[i] = *(const float4*)(emb + (size_t)word*Dn + lane*4);
        }
    }

    // Fused scores: per-word dot with w_self, warp-reduced.
    #pragma unroll
    for (int i = 0; i < NWPW; i++) {
        const int w = wid + 8*i;
        if (w < Wn) {
            float p = e[i].x*ws4.x + e[i].y*ws4.y + e[i].z*ws4.z + e[i].w*ws4.w;
            #pragma unroll
            for (int off = 16; off > 0; off >>= 1)
                p += __shfl_xor_sync(0xffffffffu, p, off);
            if (lane == 0) sscore[w] = tanhf(p + bs);
        }
    }
    __syncthreads();

    // Softmax over 100 words (warp 0). tanh output is in [-1,1]: exp is safe
    // without max subtraction (softmax is shift-invariant -> identical result).
    if (wid == 0) {
        float s = 0.f;
        float ebuf[4];
        #pragma unroll
        for (int j = 0; j < 4; j++) {
            const int i = lane + 32*j;
            if (i < Wn) {
                ebuf[j] = __expf(sscore[i]);
                s += ebuf[j];
            }
        }
        #pragma unroll
        for (int off = 16; off > 0; off >>= 1)
            s += __shfl_xor_sync(0xffffffffu, s, off);
        const float inv = 1.f / s;
        #pragma unroll
        for (int j = 0; j < 4; j++) {
            const int i = lane + 32*j;
            if (i < Wn) sscore[i] = ebuf[j] * inv;
        }
    }
    __syncthreads();

    // Weighted sum from registers; per-warp partial -> smem float4 store.
    float4 acc = make_float4(0.f, 0.f, 0.f, 0.f);
    #pragma unroll
    for (int i = 0; i < NWPW; i++) {
        const int w = wid + 8*i;
        if (w < Wn) {
            const float s = sscore[w];   // lane-uniform LDS broadcast
            acc.x += s * e[i].x;
            acc.y += s * e[i].y;
            acc.z += s * e[i].z;
            acc.w += s * e[i].w;
        }
    }
    *(float4*)(&spart[wid][lane*4]) = acc;
    __syncthreads();

    // Final 8-way cross-warp reduce (128 threads, padded rows: no conflicts).
    if (tid < Dn) {
        float r = 0.f;
        #pragma unroll
        for (int w = 0; w < 8; w++) r += spart[w][tid];
        outp[tid] = r;
    }
}

// ---------------------------------------------------------------------------
// Kernel 2: fused  V[b,d] = sum_h tanh(q_b . Wq[:, d*64+h] + bq) * w_red[h]
// Batch-tiled GEMM (BT=32 batches reuse each Wq element), col tile CT=128.
// pq (8 MB) is never materialized.
// ---------------------------------------------------------------------------
__global__ void pq_kernel(const float* __restrict__ Wq,
                          const float* __restrict__ bq,
                          const float* __restrict__ w_red) {
    __shared__ __align__(16) float QsT[Dn][BT + 4];   // transposed, padded
    __shared__ float red[BT][CT + 1];

    const int tid  = threadIdx.x;        // 128 threads
    const int col0 = blockIdx.x * CT;
    const int b0   = blockIdx.y * BT;

    #pragma unroll 4
    for (int b = 0; b < BT; b++)
        QsT[tid][b] = g_q_emb[(b0 + b)*Dn + tid];
    __syncthreads();

    float acc[BT];
    #pragma unroll
    for (int b = 0; b < BT; b++) acc[b] = 0.f;

    const int col = col0 + tid;
    const float* wqp = Wq + col;
    #pragma unroll 4
    for (int k = 0; k < Dn; k++) {
        const float wv = wqp[(size_t)k * NCOL];
        const float4* q4 = (const float4*)(&QsT[k][0]);
        #pragma unroll
        for (int i = 0; i < BT/4; i++) {
            float4 q = q4[i];
            acc[4*i+0] += q.x * wv;
            acc[4*i+1] += q.y * wv;
            acc[4*i+2] += q.z * wv;
            acc[4*i+3] += q.w * wv;
        }
    }

    const float bqv = bq[col];
    const float wr  = w_red[col & (Hn-1)];
    #pragma unroll
    for (int b = 0; b < BT; b++)
        red[b][tid] = tanhf(acc[b] + bqv) * wr;
    __syncthreads();

    // Reduce groups of 64 cols: 64 sums, 2 threads each
    const int s    = tid >> 1;      // 0..63
    const int b    = s >> 1;        // 0..31
    const int grp  = s & 1;
    const int part = tid & 1;
    float r = 0.f;
    const int base = grp*64 + part*32;
    #pragma unroll
    for (int j = 0; j < 32; j++) r += red[b][base + j];
    r += __shfl_xor_sync(0xffffffffu, r, 1);
    if (part == 0) {
        const int dd = (col0 >> 6) + grp;
        g_V[(b0 + b)*Dn + dd] = r;
    }
}

// ---------------------------------------------------------------------------
// Kernel 3: review attention (softmax over R=20) + final outputs
// One block per batch.
// ---------------------------------------------------------------------------
__global__ void attn_kernel(const float* __restrict__ pf_ptr,
                            float* __restrict__ out) {
    __shared__ float v[Dn];
    __shared__ float r_u[32], r_i[32];
    const int tid  = threadIdx.x;   // 128
    const int lane = tid & 31;
    const int wid  = tid >> 5;
    const int b    = blockIdx.x;

    v[tid] = g_V[b*Dn + tid];
    __syncthreads();

    for (int rr = wid; rr < Rn; rr += 4) {
        const float* ue = g_user_emb + (b*Rn + rr)*Dn;
        const float* ie = g_item_emb + (b*Rn + rr)*Dn;
        float pu = 0.f, pi = 0.f;
        #pragma unroll
        for (int j = 0; j < 4; j++) {
            const int d = lane + 32*j;
            const float vv = v[d];
            pu += ue[d]*vv;
            pi += ie[d]*vv;
        }
        #pragma unroll
        for (int off = 16; off > 0; off >>= 1) {
            pu += __shfl_xor_sync(0xffffffffu, pu, off);
            pi += __shfl_xor_sync(0xffffffffu, pi, off);
        }
        if (lane == 0) { r_u[rr] = pu; r_i[rr] = pi; }
    }
    __syncthreads();

    if (wid < 2) {
        float* rs = wid ? r_i : r_u;
        float x = (lane < Rn) ? rs[lane] : -1e30f;
        float m = x;
        #pragma unroll
        for (int off = 16; off > 0; off >>= 1)
            m = fmaxf(m, __shfl_xor_sync(0xffffffffu, m, off));
        float e = (lane < Rn) ? __expf(x - m) : 0.f;
        float ss = e;
        #pragma unroll
        for (int off = 16; off > 0; off >>= 1)
            ss += __shfl_xor_sync(0xffffffffu, ss, off);
        if (lane < Rn) rs[lane] = e / ss;
    }
    __syncthreads();

    float ue_acc = 0.f, ie_acc = 0.f;
    #pragma unroll
    for (int rr = 0; rr < Rn; rr++) {
        ue_acc += r_u[rr] * g_user_emb[(b*Rn + rr)*Dn + tid];
        ie_acc += r_i[rr] * g_item_emb[(b*Rn + rr)*Dn + tid];
    }
    const float pf = pf_ptr[0];
    out[b*Dn + tid]         = ue_acc + pf * g_q_emb[b*Dn + tid];
    out[Bx*Dn + b*Dn + tid] = ie_acc;
}

// ---------------------------------------------------------------------------
extern "C" void kernel_launch(void* const* d_in, const int* in_sizes, int n_in,
                              void* d_out, int out_size) {
    const int*   user   = (const int*)  d_in[0];
    const int*   item   = (const int*)  d_in[1];
    const int*   query  = (const int*)  d_in[2];
    const float* emb    = (const float*)d_in[3];
    const float* w_self = (const float*)d_in[4];
    const float* b_self = (const float*)d_in[5];
    const float* Wq     = (const float*)d_in[6];
    const float* bq     = (const float*)d_in[7];
    const float* w_red  = (const float*)d_in[8];
    const float* pf     = (const float*)d_in[9];
    float* out = (float*)d_out;

    doc_embed_kernel<<<2*Bx*Rn + Bx, 256>>>(user, item, query,
                                            emb, w_self, b_self);

    dim3 g2(NCOL/CT, Bx/BT);   // (64, 8)
    pq_kernel<<<g2, CT>>>(Wq, bq, w_red);

    attn_kernel<<<Bx, Dn>>>(pf, out);
}

// round 4
// speedup vs baseline: 1.4857x; 1.1524x over previous
#include <cuda_runtime.h>
#include <math.h>

#define Bx 256
#define Rn 20
#define Wn 100
#define Dn 128
#define Hn 64
#define NCOL (Dn*Hn)   // 8192
#define BT 32
#define CT 128
#define NRND 4         // max pair-rounds per warp: ceil(50/16)

// Scratch (allocation-free rule: __device__ globals)
__device__ float g_user_emb[Bx*Rn*Dn];   // 2.62 MB
__device__ float g_item_emb[Bx*Rn*Dn];   // 2.62 MB
__device__ float g_q_emb[Bx*Dn];         // 128 KB
__device__ float g_V[Bx*Dn];             // 128 KB

// ---------------------------------------------------------------------------
// Kernel 1: doc embedding (tanh self-attention pooling over words).
// One block (512 thr = 16 warps) per doc. Paired half-warp layout:
//   pair p -> word 2p in lanes 0-15, word 2p+1 in lanes 16-31.
//   lane l4 = lane&15 holds dims [l4*4..l4*4+3] and [64+l4*4..64+l4*4+3].
// Score reduce = 4-level butterfly within 16 lanes (2 words per 4 shfl).
// Embeddings stay in registers (<=32 data regs) across all phases.
// ---------------------------------------------------------------------------
__global__ __launch_bounds__(512, 2) void doc_embed_kernel(
        const int* __restrict__ user,
        const int* __restrict__ item,
        const int* __restrict__ query,
        const float* __restrict__ emb,
        const float* __restrict__ w_self,
        const float* __restrict__ b_self) {
    __shared__ float sscore[Wn];
    __shared__ int   swords[Wn];
    __shared__ __align__(16) float spart[16][Dn + 4];

    const int tid  = threadIdx.x;
    const int lane = tid & 31;
    const int wid  = tid >> 5;       // 0..15
    const int l4   = lane & 15;
    const int hl   = lane >> 4;      // 0 = word A, 1 = word B
    const int doc  = blockIdx.x;

    const int* words;
    float* outp;
    if (doc < Bx*Rn)        { words = user + doc*Wn;                outp = g_user_emb + doc*Dn; }
    else if (doc < 2*Bx*Rn) { int j = doc - Bx*Rn;   words = item  + j*Wn; outp = g_item_emb + j*Dn; }
    else                    { int j = doc - 2*Bx*Rn; words = query + j*Wn; outp = g_q_emb    + j*Dn; }

    if (tid < Wn) swords[tid] = words[tid];
    __syncthreads();

    // Per-lane slice of w_self (8 floats).
    const float4 wsL = *(const float4*)(w_self + l4*4);
    const float4 wsH = *(const float4*)(w_self + 64 + l4*4);
    const float  bs  = b_self[0];

    // Gather into registers: warp `wid` owns pairs wid, wid+16, wid+32, wid+48.
    float4 eL[NRND], eH[NRND];
    #pragma unroll
    for (int i = 0; i < NRND; i++) {
        const int p = wid + 16*i;
        if (p < Wn/2) {
            const int word = swords[2*p + hl];
            const float* base = emb + (size_t)word*Dn;
            eL[i] = *(const float4*)(base + l4*4);
            eH[i] = *(const float4*)(base + 64 + l4*4);
        }
    }

    // Fused scores: 8-dim partial per lane, 4-level butterfly within 16 lanes
    // reduces both words of the pair simultaneously.
    #pragma unroll
    for (int i = 0; i < NRND; i++) {
        const int p = wid + 16*i;
        if (p < Wn/2) {
            float s = eL[i].x*wsL.x + eL[i].y*wsL.y + eL[i].z*wsL.z + eL[i].w*wsL.w
                    + eH[i].x*wsH.x + eH[i].y*wsH.y + eH[i].z*wsH.z + eH[i].w*wsH.w;
            #pragma unroll
            for (int off = 8; off > 0; off >>= 1)
                s += __shfl_xor_sync(0xffffffffu, s, off);
            if (l4 == 0) sscore[2*p + hl] = tanhf(s + bs);
        }
    }
    __syncthreads();

    // Softmax over 100 words (warp 0). tanh output bounded in [-1,1]: exp is
    // safe without max subtraction (shift-invariance -> identical result).
    if (wid == 0) {
        float s = 0.f;
        float ebuf[4];
        #pragma unroll
        for (int j = 0; j < 4; j++) {
            const int i = lane + 32*j;
            if (i < Wn) { ebuf[j] = __expf(sscore[i]); s += ebuf[j]; }
        }
        #pragma unroll
        for (int off = 16; off > 0; off >>= 1)
            s += __shfl_xor_sync(0xffffffffu, s, off);
        const float inv = 1.f / s;
        #pragma unroll
        for (int j = 0; j < 4; j++) {
            const int i = lane + 32*j;
            if (i < Wn) sscore[i] = ebuf[j] * inv;
        }
    }
    __syncthreads();

    // Weighted sum from registers.
    float4 aL = make_float4(0.f,0.f,0.f,0.f);
    float4 aH = make_float4(0.f,0.f,0.f,0.f);
    #pragma unroll
    for (int i = 0; i < NRND; i++) {
        const int p = wid + 16*i;
        if (p < Wn/2) {
            const float s = sscore[2*p + hl];   // half-broadcast LDS
            aL.x += s*eL[i].x; aL.y += s*eL[i].y; aL.z += s*eL[i].z; aL.w += s*eL[i].w;
            aH.x += s*eH[i].x; aH.y += s*eH[i].y; aH.z += s*eH[i].z; aH.w += s*eH[i].w;
        }
    }
    // Combine word-A/word-B halves (same dims in lanes l and l+16).
    aL.x += __shfl_xor_sync(0xffffffffu, aL.x, 16);
    aL.y += __shfl_xor_sync(0xffffffffu, aL.y, 16);
    aL.z += __shfl_xor_sync(0xffffffffu, aL.z, 16);
    aL.w += __shfl_xor_sync(0xffffffffu, aL.w, 16);
    aH.x += __shfl_xor_sync(0xffffffffu, aH.x, 16);
    aH.y += __shfl_xor_sync(0xffffffffu, aH.y, 16);
    aH.z += __shfl_xor_sync(0xffffffffu, aH.z, 16);
    aH.w += __shfl_xor_sync(0xffffffffu, aH.w, 16);
    if (hl == 0) {
        *(float4*)(&spart[wid][l4*4])      = aL;
        *(float4*)(&spart[wid][64 + l4*4]) = aH;
    }
    __syncthreads();

    // Final 16-way cross-warp reduce (128 threads).
    if (tid < Dn) {
        float r = 0.f;
        #pragma unroll
        for (int w = 0; w < 16; w++) r += spart[w][tid];
        outp[tid] = r;
    }
}

// ---------------------------------------------------------------------------
// Kernel 2: fused  V[b,d] = sum_h tanh(q_b . Wq[:, d*64+h] + bq) * w_red[h]
// Batch-tiled GEMM (BT=32 batches reuse each Wq element), col tile CT=128.
// pq (8 MB) is never materialized.
// ---------------------------------------------------------------------------
__global__ void pq_kernel(const float* __restrict__ Wq,
                          const float* __restrict__ bq,
                          const float* __restrict__ w_red) {
    __shared__ __align__(16) float QsT[Dn][BT + 4];   // transposed, padded
    __shared__ float red[BT][CT + 1];

    const int tid  = threadIdx.x;        // 128 threads
    const int col0 = blockIdx.x * CT;
    const int b0   = blockIdx.y * BT;

    #pragma unroll 4
    for (int b = 0; b < BT; b++)
        QsT[tid][b] = g_q_emb[(b0 + b)*Dn + tid];
    __syncthreads();

    float acc[BT];
    #pragma unroll
    for (int b = 0; b < BT; b++) acc[b] = 0.f;

    const int col = col0 + tid;
    const float* wqp = Wq + col;
    #pragma unroll 4
    for (int k = 0; k < Dn; k++) {
        const float wv = wqp[(size_t)k * NCOL];
        const float4* q4 = (const float4*)(&QsT[k][0]);
        #pragma unroll
        for (int i = 0; i < BT/4; i++) {
            float4 q = q4[i];
            acc[4*i+0] += q.x * wv;
            acc[4*i+1] += q.y * wv;
            acc[4*i+2] += q.z * wv;
            acc[4*i+3] += q.w * wv;
        }
    }

    const float bqv = bq[col];
    const float wr  = w_red[col & (Hn-1)];
    #pragma unroll
    for (int b = 0; b < BT; b++)
        red[b][tid] = tanhf(acc[b] + bqv) * wr;
    __syncthreads();

    // Reduce groups of 64 cols: 64 sums, 2 threads each
    const int s    = tid >> 1;      // 0..63
    const int b    = s >> 1;        // 0..31
    const int grp  = s & 1;
    const int part = tid & 1;
    float r = 0.f;
    const int base = grp*64 + part*32;
    #pragma unroll
    for (int j = 0; j < 32; j++) r += red[b][base + j];
    r += __shfl_xor_sync(0xffffffffu, r, 1);
    if (part == 0) {
        const int dd = (col0 >> 6) + grp;
        g_V[(b0 + b)*Dn + dd] = r;
    }
}

// ---------------------------------------------------------------------------
// Kernel 3: review attention (softmax over R=20) + final outputs
// One block per batch.
// ---------------------------------------------------------------------------
__global__ void attn_kernel(const float* __restrict__ pf_ptr,
                            float* __restrict__ out) {
    __shared__ float v[Dn];
    __shared__ float r_u[32], r_i[32];
    const int tid  = threadIdx.x;   // 128
    const int lane = tid & 31;
    const int wid  = tid >> 5;
    const int b    = blockIdx.x;

    v[tid] = g_V[b*Dn + tid];
    __syncthreads();

    for (int rr = wid; rr < Rn; rr += 4) {
        const float* ue = g_user_emb + (b*Rn + rr)*Dn;
        const float* ie = g_item_emb + (b*Rn + rr)*Dn;
        float pu = 0.f, pi = 0.f;
        #pragma unroll
        for (int j = 0; j < 4; j++) {
            const int d = lane + 32*j;
            const float vv = v[d];
            pu += ue[d]*vv;
            pi += ie[d]*vv;
        }
        #pragma unroll
        for (int off = 16; off > 0; off >>= 1) {
            pu += __shfl_xor_sync(0xffffffffu, pu, off);
            pi += __shfl_xor_sync(0xffffffffu, pi, off);
        }
        if (lane == 0) { r_u[rr] = pu; r_i[rr] = pi; }
    }
    __syncthreads();

    if (wid < 2) {
        float* rs = wid ? r_i : r_u;
        float x = (lane < Rn) ? rs[lane] : -1e30f;
        float m = x;
        #pragma unroll
        for (int off = 16; off > 0; off >>= 1)
            m = fmaxf(m, __shfl_xor_sync(0xffffffffu, m, off));
        float e = (lane < Rn) ? __expf(x - m) : 0.f;
        float ss = e;
        #pragma unroll
        for (int off = 16; off > 0; off >>= 1)
            ss += __shfl_xor_sync(0xffffffffu, ss, off);
        if (lane < Rn) rs[lane] = e / ss;
    }
    __syncthreads();

    float ue_acc = 0.f, ie_acc = 0.f;
    #pragma unroll
    for (int rr = 0; rr < Rn; rr++) {
        ue_acc += r_u[rr] * g_user_emb[(b*Rn + rr)*Dn + tid];
        ie_acc += r_i[rr] * g_item_emb[(b*Rn + rr)*Dn + tid];
    }
    const float pf = pf_ptr[0];
    out[b*Dn + tid]         = ue_acc + pf * g_q_emb[b*Dn + tid];
    out[Bx*Dn + b*Dn + tid] = ie_acc;
}

// ---------------------------------------------------------------------------
extern "C" void kernel_launch(void* const* d_in, const int* in_sizes, int n_in,
                              void* d_out, int out_size) {
    const int*   user   = (const int*)  d_in[0];
    const int*   item   = (const int*)  d_in[1];
    const int*   query  = (const int*)  d_in[2];
    const float* emb    = (const float*)d_in[3];
    const float* w_self = (const float*)d_in[4];
    const float* b_self = (const float*)d_in[5];
    const float* Wq     = (const float*)d_in[6];
    const float* bq     = (const float*)d_in[7];
    const float* w_red  = (const float*)d_in[8];
    const float* pf     = (const float*)d_in[9];
    float* out = (float*)d_out;

    doc_embed_kernel<<<2*Bx*Rn + Bx, 512>>>(user, item, query,
                                            emb, w_self, b_self);

    dim3 g2(NCOL/CT, Bx/BT);   // (64, 8)
    pq_kernel<<<g2, CT>>>(Wq, bq, w_red);

    attn_kernel<<<Bx, Dn>>>(pf, out);
}

// round 5
// speedup vs baseline: 1.5678x; 1.0553x over previous
#include <cuda_runtime.h>
#include <math.h>

#define Bx 256
#define Rn 20
#define Wn 100
#define Dn 128
#define Hn 64
#define NCOL (Dn*Hn)   // 8192
#define BT 32
#define CT 128
#define NRND 4         // max pair-rounds per warp: ceil(50/16)
#define PS 20          // spsc row stride (floats): conflict-free LDS.128 reads

// Scratch (allocation-free rule: __device__ globals)
__device__ float g_user_emb[Bx*Rn*Dn];   // 2.62 MB
__device__ float g_item_emb[Bx*Rn*Dn];   // 2.62 MB
__device__ float g_q_emb[Bx*Dn];         // 128 KB
__device__ float g_V[Bx*Dn];             // 128 KB

// ---------------------------------------------------------------------------
// Kernel 1: doc embedding (tanh self-attention pooling over words).
// One block (512 thr = 16 warps) per doc. Paired half-warp layout:
//   pair p -> word 2p in lanes 0-15, word 2p+1 in lanes 16-31;
//   lane l4 holds dims [l4*4..+3] and [64+l4*4..+3] (registers, all phases).
// Score path is SHUFFLE-FREE: per-lane partials -> smem -> 100 threads
// finish tanh scores. Softmax sum computed redundantly per-warp (identical
// op order -> bitwise-identical inv), weights normalized inline.
// ---------------------------------------------------------------------------
__global__ __launch_bounds__(512, 2) void doc_embed_kernel(
        const int* __restrict__ user,
        const int* __restrict__ item,
        const int* __restrict__ query,
        const float* __restrict__ emb,
        const float* __restrict__ w_self,
        const float* __restrict__ b_self) {
    __shared__ __align__(16) float spsc[Wn][PS];      // 8 KB score partials
    __shared__ float sscore[Wn];                      // raw tanh scores
    __shared__ int   swords[Wn];
    __shared__ __align__(16) float spart[16][Dn + 4]; // 8.4 KB warp partials

    const int tid  = threadIdx.x;
    const int lane = tid & 31;
    const int wid  = tid >> 5;       // 0..15
    const int l4   = lane & 15;
    const int hl   = lane >> 4;      // 0 = word A, 1 = word B
    const int doc  = blockIdx.x;

    const int* words;
    float* outp;
    if (doc < Bx*Rn)        { words = user + doc*Wn;                outp = g_user_emb + doc*Dn; }
    else if (doc < 2*Bx*Rn) { int j = doc - Bx*Rn;   words = item  + j*Wn; outp = g_item_emb + j*Dn; }
    else                    { int j = doc - 2*Bx*Rn; words = query + j*Wn; outp = g_q_emb    + j*Dn; }

    if (tid < Wn) swords[tid] = words[tid];
    __syncthreads();

    // Per-lane slice of w_self (8 floats).
    const float4 wsL = *(const float4*)(w_self + l4*4);
    const float4 wsH = *(const float4*)(w_self + 64 + l4*4);
    const float  bs  = b_self[0];

    // Gather into registers: warp `wid` owns pairs wid, wid+16, wid+32, wid+48.
    float4 eL[NRND], eH[NRND];
    #pragma unroll
    for (int i = 0; i < NRND; i++) {
        const int p = wid + 16*i;
        if (p < Wn/2) {
            const int word = swords[2*p + hl];
            const float* base = emb + (size_t)word*Dn;
            eL[i] = *(const float4*)(base + l4*4);
            eH[i] = *(const float4*)(base + 64 + l4*4);
        }
    }

    // Score partials: 8-dim dot per lane -> smem. No shuffles, no result
    // latency (BAR drains STS).
    #pragma unroll
    for (int i = 0; i < NRND; i++) {
        const int p = wid + 16*i;
        if (p < Wn/2) {
            float s = eL[i].x*wsL.x + eL[i].y*wsL.y + eL[i].z*wsL.z + eL[i].w*wsL.w
                    + eH[i].x*wsH.x + eH[i].y*wsH.y + eH[i].z*wsH.z + eH[i].w*wsH.w;
            spsc[2*p + hl][l4] = s;
        }
    }
    __syncthreads();

    // 100 threads finish the scores: 4 independent LDS.128 + add tree + tanh.
    if (tid < Wn) {
        const float4* row = (const float4*)(&spsc[tid][0]);
        float4 a = row[0], b = row[1], c = row[2], d = row[3];
        float s = ((a.x + a.y) + (a.z + a.w)) + ((b.x + b.y) + (b.z + b.w))
                + ((c.x + c.y) + (c.z + c.w)) + ((d.x + d.y) + (d.z + d.w));
        sscore[tid] = tanhf(s + bs);
    }
    __syncthreads();

    // Redundant per-warp softmax denominator (tanh in [-1,1]: exp safe without
    // max-shift; shift-invariance -> identical result). Same op order in every
    // warp -> identical inv.
    float ssum = 0.f;
    {
        float e0 = __expf(sscore[lane]);
        float e1 = __expf(sscore[lane + 32]);
        float e2 = __expf(sscore[lane + 64]);
        float e3 = (lane < Wn - 96) ? __expf(sscore[lane + 96]) : 0.f;
        ssum = (e0 + e1) + (e2 + e3);
        #pragma unroll
        for (int off = 16; off > 0; off >>= 1)
            ssum += __shfl_xor_sync(0xffffffffu, ssum, off);
    }
    const float inv = 1.f / ssum;

    // Weighted sum from registers, weights normalized inline.
    float4 aL = make_float4(0.f,0.f,0.f,0.f);
    float4 aH = make_float4(0.f,0.f,0.f,0.f);
    #pragma unroll
    for (int i = 0; i < NRND; i++) {
        const int p = wid + 16*i;
        if (p < Wn/2) {
            const float s = __expf(sscore[2*p + hl]) * inv;
            aL.x += s*eL[i].x; aL.y += s*eL[i].y; aL.z += s*eL[i].z; aL.w += s*eL[i].w;
            aH.x += s*eH[i].x; aH.y += s*eH[i].y; aH.z += s*eH[i].z; aH.w += s*eH[i].w;
        }
    }
    // Combine word-A/word-B halves (same dims in lanes l and l+16);
    // 4 independent pairs -> ~2 shfl of latency depth.
    aL.x += __shfl_xor_sync(0xffffffffu, aL.x, 16);
    aL.y += __shfl_xor_sync(0xffffffffu, aL.y, 16);
    aL.z += __shfl_xor_sync(0xffffffffu, aL.z, 16);
    aL.w += __shfl_xor_sync(0xffffffffu, aL.w, 16);
    aH.x += __shfl_xor_sync(0xffffffffu, aH.x, 16);
    aH.y += __shfl_xor_sync(0xffffffffu, aH.y, 16);
    aH.z += __shfl_xor_sync(0xffffffffu, aH.z, 16);
    aH.w += __shfl_xor_sync(0xffffffffu, aH.w, 16);
    if (hl == 0) {
        *(float4*)(&spart[wid][l4*4])      = aL;
        *(float4*)(&spart[wid][64 + l4*4]) = aH;
    }
    __syncthreads();

    // Final 16-way cross-warp reduce (128 threads).
    if (tid < Dn) {
        float r = 0.f;
        #pragma unroll
        for (int w = 0; w < 16; w++) r += spart[w][tid];
        outp[tid] = r;
    }
}

// ---------------------------------------------------------------------------
// Kernel 2: fused  V[b,d] = sum_h tanh(q_b . Wq[:, d*64+h] + bq) * w_red[h]
// Batch-tiled GEMM (BT=32 batches reuse each Wq element), col tile CT=128.
// pq (8 MB) is never materialized.
// ---------------------------------------------------------------------------
__global__ void pq_kernel(const float* __restrict__ Wq,
                          const float* __restrict__ bq,
                          const float* __restrict__ w_red) {
    __shared__ __align__(16) float QsT[Dn][BT + 4];   // transposed, padded
    __shared__ float red[BT][CT + 1];

    const int tid  = threadIdx.x;        // 128 threads
    const int col0 = blockIdx.x * CT;
    const int b0   = blockIdx.y * BT;

    #pragma unroll 4
    for (int b = 0; b < BT; b++)
        QsT[tid][b] = g_q_emb[(b0 + b)*Dn + tid];
    __syncthreads();

    float acc[BT];
    #pragma unroll
    for (int b = 0; b < BT; b++) acc[b] = 0.f;

    const int col = col0 + tid;
    const float* wqp = Wq + col;
    #pragma unroll 4
    for (int k = 0; k < Dn; k++) {
        const float wv = wqp[(size_t)k * NCOL];
        const float4* q4 = (const float4*)(&QsT[k][0]);
        #pragma unroll
        for (int i = 0; i < BT/4; i++) {
            float4 q = q4[i];
            acc[4*i+0] += q.x * wv;
            acc[4*i+1] += q.y * wv;
            acc[4*i+2] += q.z * wv;
            acc[4*i+3] += q.w * wv;
        }
    }

    const float bqv = bq[col];
    const float wr  = w_red[col & (Hn-1)];
    #pragma unroll
    for (int b = 0; b < BT; b++)
        red[b][tid] = tanhf(acc[b] + bqv) * wr;
    __syncthreads();

    // Reduce groups of 64 cols: 64 sums, 2 threads each
    const int s    = tid >> 1;      // 0..63
    const int b    = s >> 1;        // 0..31
    const int grp  = s & 1;
    const int part = tid & 1;
    float r = 0.f;
    const int base = grp*64 + part*32;
    #pragma unroll
    for (int j = 0; j < 32; j++) r += red[b][base + j];
    r += __shfl_xor_sync(0xffffffffu, r, 1);
    if (part == 0) {
        const int dd = (col0 >> 6) + grp;
        g_V[(b0 + b)*Dn + dd] = r;
    }
}

// ---------------------------------------------------------------------------
// Kernel 3: review attention (softmax over R=20) + final outputs
// One block per batch.
// ---------------------------------------------------------------------------
__global__ void attn_kernel(const float* __restrict__ pf_ptr,
                            float* __restrict__ out) {
    __shared__ float v[Dn];
    __shared__ float r_u[32], r_i[32];
    const int tid  = threadIdx.x;   // 128
    const int lane = tid & 31;
    const int wid  = tid >> 5;
    const int b    = blockIdx.x;

    v[tid] = g_V[b*Dn + tid];
    __syncthreads();

    for (int rr = wid; rr < Rn; rr += 4) {
        const float* ue = g_user_emb + (b*Rn + rr)*Dn;
        const float* ie = g_item_emb + (b*Rn + rr)*Dn;
        float pu = 0.f, pi = 0.f;
        #pragma unroll
        for (int j = 0; j < 4; j++) {
            const int d = lane + 32*j;
            const float vv = v[d];
            pu += ue[d]*vv;
            pi += ie[d]*vv;
        }
        #pragma unroll
        for (int off = 16; off > 0; off >>= 1) {
            pu += __shfl_xor_sync(0xffffffffu, pu, off);
            pi += __shfl_xor_sync(0xffffffffu, pi, off);
        }
        if (lane == 0) { r_u[rr] = pu; r_i[rr] = pi; }
    }
    __syncthreads();

    if (wid < 2) {
        float* rs = wid ? r_i : r_u;
        float x = (lane < Rn) ? rs[lane] : -1e30f;
        float m = x;
        #pragma unroll
        for (int off = 16; off > 0; off >>= 1)
            m = fmaxf(m, __shfl_xor_sync(0xffffffffu, m, off));
        float e = (lane < Rn) ? __expf(x - m) : 0.f;
        float ss = e;
        #pragma unroll
        for (int off = 16; off > 0; off >>= 1)
            ss += __shfl_xor_sync(0xffffffffu, ss, off);
        if (lane < Rn) rs[lane] = e / ss;
    }
    __syncthreads();

    float ue_acc = 0.f, ie_acc = 0.f;
    #pragma unroll
    for (int rr = 0; rr < Rn; rr++) {
        ue_acc += r_u[rr] * g_user_emb[(b*Rn + rr)*Dn + tid];
        ie_acc += r_i[rr] * g_item_emb[(b*Rn + rr)*Dn + tid];
    }
    const float pf = pf_ptr[0];
    out[b*Dn + tid]         = ue_acc + pf * g_q_emb[b*Dn + tid];
    out[Bx*Dn + b*Dn + tid] = ie_acc;
}

// ---------------------------------------------------------------------------
extern "C" void kernel_launch(void* const* d_in, const int* in_sizes, int n_in,
                              void* d_out, int out_size) {
    const int*   user   = (const int*)  d_in[0];
    const int*   item   = (const int*)  d_in[1];
    const int*   query  = (const int*)  d_in[2];
    const float* emb    = (const float*)d_in[3];
    const float* w_self = (const float*)d_in[4];
    const float* b_self = (const float*)d_in[5];
    const float* Wq     = (const float*)d_in[6];
    const float* bq     = (const float*)d_in[7];
    const float* w_red  = (const float*)d_in[8];
    const float* pf     = (const float*)d_in[9];
    float* out = (float*)d_out;

    doc_embed_kernel<<<2*Bx*Rn + Bx, 512>>>(user, item, query,
                                            emb, w_self, b_self);

    dim3 g2(NCOL/CT, Bx/BT);   // (64, 8)
    pq_kernel<<<g2, CT>>>(Wq, bq, w_red);

    attn_kernel<<<Bx, Dn>>>(pf, out);
}

// round 6
// speedup vs baseline: 1.7035x; 1.0866x over previous
#include <cuda_runtime.h>
#include <math.h>

#define Bx 256
#define Rn 20
#define Wn 100
#define Dn 128
#define Hn 64
#define NCOL (Dn*Hn)   // 8192
#define BT 32
#define CT 128
#define NRND 4         // max pair-rounds per warp: ceil(50/16)
#define PS 20          // spsc row stride (floats): 16B-aligned float4 reads

// Scratch (allocation-free rule: __device__ globals)
__device__ float g_user_emb[Bx*Rn*Dn];   // 2.62 MB
__device__ float g_item_emb[Bx*Rn*Dn];   // 2.62 MB
__device__ float g_q_emb[Bx*Dn];         // 128 KB
__device__ float g_V[Bx*Dn];             // 128 KB

// ---------------------------------------------------------------------------
// Kernel 1: doc embedding (tanh self-attention pooling over words).
// One block (512 thr = 16 warps) per doc. Paired half-warp layout:
//   pair p -> word 2p in lanes 0-15, word 2p+1 in lanes 16-31;
//   lane l4 holds dims [l4*4..+3] and [64+l4*4..+3] (registers, all phases).
// MUFU-minimal: exp/tanh computed ONCE per word (200 MUFU/doc); softmax
// normalization is linear so it's deferred to the final reduce (r/ssum).
// ---------------------------------------------------------------------------
__global__ __launch_bounds__(512, 2) void doc_embed_kernel(
        const int* __restrict__ user,
        const int* __restrict__ item,
        const int* __restrict__ query,
        const float* __restrict__ emb,
        const float* __restrict__ w_self,
        const float* __restrict__ b_self) {
    __shared__ __align__(16) float spsc[Wn][PS];      // 8 KB score partials
    __shared__ float sscore[Wn];                      // exp(tanh) per word
    __shared__ int   swords[Wn];
    __shared__ __align__(16) float spart[16][Dn + 4]; // 8.4 KB warp partials

    const int tid  = threadIdx.x;
    const int lane = tid & 31;
    const int wid  = tid >> 5;       // 0..15
    const int l4   = lane & 15;
    const int hl   = lane >> 4;      // 0 = word A, 1 = word B
    const int doc  = blockIdx.x;

    const int* words;
    float* outp;
    if (doc < Bx*Rn)        { words = user + doc*Wn;                outp = g_user_emb + doc*Dn; }
    else if (doc < 2*Bx*Rn) { int j = doc - Bx*Rn;   words = item  + j*Wn; outp = g_item_emb + j*Dn; }
    else                    { int j = doc - 2*Bx*Rn; words = query + j*Wn; outp = g_q_emb    + j*Dn; }

    if (tid < Wn) swords[tid] = words[tid];
    __syncthreads();

    // Per-lane slice of w_self (8 floats).
    const float4 wsL = *(const float4*)(w_self + l4*4);
    const float4 wsH = *(const float4*)(w_self + 64 + l4*4);
    const float  bs  = b_self[0];

    // Gather into registers: warp `wid` owns pairs wid, wid+16, wid+32, wid+48.
    float4 eL[NRND], eH[NRND];
    #pragma unroll
    for (int i = 0; i < NRND; i++) {
        const int p = wid + 16*i;
        if (p < Wn/2) {
            const int word = swords[2*p + hl];
            const float* base = emb + (size_t)word*Dn;
            eL[i] = *(const float4*)(base + l4*4);
            eH[i] = *(const float4*)(base + 64 + l4*4);
        }
    }

    // Score partials: 8-dim dot per lane -> smem. No shuffles; BAR drains STS.
    #pragma unroll
    for (int i = 0; i < NRND; i++) {
        const int p = wid + 16*i;
        if (p < Wn/2) {
            float s = eL[i].x*wsL.x + eL[i].y*wsL.y + eL[i].z*wsL.z + eL[i].w*wsL.w
                    + eH[i].x*wsH.x + eH[i].y*wsH.y + eH[i].z*wsH.z + eH[i].w*wsH.w;
            spsc[2*p + hl][l4] = s;
        }
    }
    __syncthreads();

    // 100 threads finish scores: reduce 16 partials, tanh, exp — the ONLY
    // MUFU in the kernel (tanh in [-1,1] -> exp safe without max-shift;
    // softmax shift-invariance keeps the result identical).
    if (tid < Wn) {
        const float4* row = (const float4*)(&spsc[tid][0]);
        float4 a = row[0], b = row[1], c = row[2], d = row[3];
        float s = ((a.x + a.y) + (a.z + a.w)) + ((b.x + b.y) + (b.z + b.w))
                + ((c.x + c.y) + (c.z + c.w)) + ((d.x + d.y) + (d.z + d.w));
        sscore[tid] = __expf(tanhf(s + bs));
    }
    __syncthreads();

    // Weighted sum with UN-normalized weights (normalization deferred).
    float4 aL = make_float4(0.f,0.f,0.f,0.f);
    float4 aH = make_float4(0.f,0.f,0.f,0.f);
    #pragma unroll
    for (int i = 0; i < NRND; i++) {
        const int p = wid + 16*i;
        if (p < Wn/2) {
            const float s = sscore[2*p + hl];   // half-warp broadcast LDS
            aL.x += s*eL[i].x; aL.y += s*eL[i].y; aL.z += s*eL[i].z; aL.w += s*eL[i].w;
            aH.x += s*eH[i].x; aH.y += s*eH[i].y; aH.z += s*eH[i].z; aH.w += s*eH[i].w;
        }
    }
    // Combine word-A/word-B halves (same dims in lanes l and l+16).
    aL.x += __shfl_xor_sync(0xffffffffu, aL.x, 16);
    aL.y += __shfl_xor_sync(0xffffffffu, aL.y, 16);
    aL.z += __shfl_xor_sync(0xffffffffu, aL.z, 16);
    aL.w += __shfl_xor_sync(0xffffffffu, aL.w, 16);
    aH.x += __shfl_xor_sync(0xffffffffu, aH.x, 16);
    aH.y += __shfl_xor_sync(0xffffffffu, aH.y, 16);
    aH.z += __shfl_xor_sync(0xffffffffu, aH.z, 16);
    aH.w += __shfl_xor_sync(0xffffffffu, aH.w, 16);
    if (hl == 0) {
        *(float4*)(&spart[wid][l4*4])      = aL;
        *(float4*)(&spart[wid][64 + l4*4]) = aH;
    }
    __syncthreads();

    // Final: warps 0-3 compute the softmax denominator redundantly (LDS+SHFL,
    // no MUFU, identical op order per warp), reduce 16 partials, divide once.
    if (tid < Dn) {
        float e0 = sscore[lane];
        float e1 = sscore[lane + 32];
        float e2 = sscore[lane + 64];
        float e3 = (lane < Wn - 96) ? sscore[lane + 96] : 0.f;
        float ssum = (e0 + e1) + (e2 + e3);
        #pragma unroll
        for (int off = 16; off > 0; off >>= 1)
            ssum += __shfl_xor_sync(0xffffffffu, ssum, off);

        float r = 0.f;
        #pragma unroll
        for (int w = 0; w < 16; w++) r += spart[w][tid];
        outp[tid] = r / ssum;
    }
}

// ---------------------------------------------------------------------------
// Kernel 2: fused  V[b,d] = sum_h tanh(q_b . Wq[:, d*64+h] + bq) * w_red[h]
// Batch-tiled GEMM (BT=32 batches reuse each Wq element), col tile CT=128.
// pq (8 MB) is never materialized.
// ---------------------------------------------------------------------------
__global__ void pq_kernel(const float* __restrict__ Wq,
                          const float* __restrict__ bq,
                          const float* __restrict__ w_red) {
    __shared__ __align__(16) float QsT[Dn][BT + 4];   // transposed, padded
    __shared__ float red[BT][CT + 1];

    const int tid  = threadIdx.x;        // 128 threads
    const int col0 = blockIdx.x * CT;
    const int b0   = blockIdx.y * BT;

    #pragma unroll 4
    for (int b = 0; b < BT; b++)
        QsT[tid][b] = g_q_emb[(b0 + b)*Dn + tid];
    __syncthreads();

    float acc[BT];
    #pragma unroll
    for (int b = 0; b < BT; b++) acc[b] = 0.f;

    const int col = col0 + tid;
    const float* wqp = Wq + col;
    #pragma unroll 4
    for (int k = 0; k < Dn; k++) {
        const float wv = wqp[(size_t)k * NCOL];
        const float4* q4 = (const float4*)(&QsT[k][0]);
        #pragma unroll
        for (int i = 0; i < BT/4; i++) {
            float4 q = q4[i];
            acc[4*i+0] += q.x * wv;
            acc[4*i+1] += q.y * wv;
            acc[4*i+2] += q.z * wv;
            acc[4*i+3] += q.w * wv;
        }
    }

    const float bqv = bq[col];
    const float wr  = w_red[col & (Hn-1)];
    #pragma unroll
    for (int b = 0; b < BT; b++)
        red[b][tid] = tanhf(acc[b] + bqv) * wr;
    __syncthreads();

    // Reduce groups of 64 cols: 64 sums, 2 threads each
    const int s    = tid >> 1;      // 0..63
    const int b    = s >> 1;        // 0..31
    const int grp  = s & 1;
    const int part = tid & 1;
    float r = 0.f;
    const int base = grp*64 + part*32;
    #pragma unroll
    for (int j = 0; j < 32; j++) r += red[b][base + j];
    r += __shfl_xor_sync(0xffffffffu, r, 1);
    if (part == 0) {
        const int dd = (col0 >> 6) + grp;
        g_V[(b0 + b)*Dn + dd] = r;
    }
}

// ---------------------------------------------------------------------------
// Kernel 3: review attention (softmax over R=20) + final outputs
// One block per batch.
// ---------------------------------------------------------------------------
__global__ void attn_kernel(const float* __restrict__ pf_ptr,
                            float* __restrict__ out) {
    __shared__ float v[Dn];
    __shared__ float r_u[32], r_i[32];
    const int tid  = threadIdx.x;   // 128
    const int lane = tid & 31;
    const int wid  = tid >> 5;
    const int b    = blockIdx.x;

    v[tid] = g_V[b*Dn + tid];
    __syncthreads();

    for (int rr = wid; rr < Rn; rr += 4) {
        const float* ue = g_user_emb + (b*Rn + rr)*Dn;
        const float* ie = g_item_emb + (b*Rn + rr)*Dn;
        float pu = 0.f, pi = 0.f;
        #pragma unroll
        for (int j = 0; j < 4; j++) {
            const int d = lane + 32*j;
            const float vv = v[d];
            pu += ue[d]*vv;
            pi += ie[d]*vv;
        }
        #pragma unroll
        for (int off = 16; off > 0; off >>= 1) {
            pu += __shfl_xor_sync(0xffffffffu, pu, off);
            pi += __shfl_xor_sync(0xffffffffu, pi, off);
        }
        if (lane == 0) { r_u[rr] = pu; r_i[rr] = pi; }
    }
    __syncthreads();

    if (wid < 2) {
        float* rs = wid ? r_i : r_u;
        float x = (lane < Rn) ? rs[lane] : -1e30f;
        float m = x;
        #pragma unroll
        for (int off = 16; off > 0; off >>= 1)
            m = fmaxf(m, __shfl_xor_sync(0xffffffffu, m, off));
        float e = (lane < Rn) ? __expf(x - m) : 0.f;
        float ss = e;
        #pragma unroll
        for (int off = 16; off > 0; off >>= 1)
            ss += __shfl_xor_sync(0xffffffffu, ss, off);
        if (lane < Rn) rs[lane] = e / ss;
    }
    __syncthreads();

    float ue_acc = 0.f, ie_acc = 0.f;
    #pragma unroll
    for (int rr = 0; rr < Rn; rr++) {
        ue_acc += r_u[rr] * g_user_emb[(b*Rn + rr)*Dn + tid];
        ie_acc += r_i[rr] * g_item_emb[(b*Rn + rr)*Dn + tid];
    }
    const float pf = pf_ptr[0];
    out[b*Dn + tid]         = ue_acc + pf * g_q_emb[b*Dn + tid];
    out[Bx*Dn + b*Dn + tid] = ie_acc;
}

// ---------------------------------------------------------------------------
extern "C" void kernel_launch(void* const* d_in, const int* in_sizes, int n_in,
                              void* d_out, int out_size) {
    const int*   user   = (const int*)  d_in[0];
    const int*   item   = (const int*)  d_in[1];
    const int*   query  = (const int*)  d_in[2];
    const float* emb    = (const float*)d_in[3];
    const float* w_self = (const float*)d_in[4];
    const float* b_self = (const float*)d_in[5];
    const float* Wq     = (const float*)d_in[6];
    const float* bq     = (const float*)d_in[7];
    const float* w_red  = (const float*)d_in[8];
    const float* pf     = (const float*)d_in[9];
    float* out = (float*)d_out;

    doc_embed_kernel<<<2*Bx*Rn + Bx, 512>>>(user, item, query,
                                            emb, w_self, b_self);

    dim3 g2(NCOL/CT, Bx/BT);   // (64, 8)
    pq_kernel<<<g2, CT>>>(Wq, bq, w_red);

    attn_kernel<<<Bx, Dn>>>(pf, out);
}